// round 11
// baseline (speedup 1.0000x reference)
#include <cuda_runtime.h>
#include <cuda_bf16.h>
#include <math.h>
#include <stdint.h>

#define BATCH 4
#define CCH   64
#define NN    4096
#define DQK   8
#define FCH   16

// ---------------- scratch ------------------------------------------------------
__device__ float g_q [BATCH*DQK*NN];            // tf32 bits, [b][d][i]
__device__ float g_k [BATCH*NN*DQK];            // tf32 bits, [b][j][d]
__device__ __nv_bfloat16 g_v [BATCH*CCH*NN];    // bf16 [b][c][j]
__device__ float g_e [BATCH*FCH*NN];
__device__ float g_ev[BATCH*FCH*NN];
__device__ float g_y2[BATCH*FCH*400];
__device__ float g_y4[BATCH*CCH*100];

__device__ __forceinline__ float to_tf32(float x){
    uint32_t r;
    asm("cvt.rna.tf32.f32 %0, %1;" : "=r"(r) : "f"(x));
    return __uint_as_float(r);
}
__device__ __forceinline__ uint32_t pack_bf16(float lo, float hi){
    uint32_t d;
    asm("cvt.rn.bf16x2.f32 %0, %1, %2;" : "=r"(d) : "f"(hi), "f"(lo));
    return d;
}
__device__ __forceinline__ float ex2f(float x){
    float r;
    asm("ex2.approx.f32 %0, %1;" : "=f"(r) : "f"(x));
    return r;
}
__device__ __forceinline__ void mma_tf32(
    float& d0, float& d1, float& d2, float& d3,
    uint32_t a0, uint32_t a1, uint32_t a2, uint32_t a3,
    uint32_t b0, uint32_t b1)
{
    asm volatile(
        "mma.sync.aligned.m16n8k8.row.col.f32.tf32.tf32.f32 "
        "{%0,%1,%2,%3},{%4,%5,%6,%7},{%8,%9},{%0,%1,%2,%3};"
        : "+f"(d0), "+f"(d1), "+f"(d2), "+f"(d3)
        : "r"(a0), "r"(a1), "r"(a2), "r"(a3), "r"(b0), "r"(b1));
}
__device__ __forceinline__ void mma_bf16(
    float& d0, float& d1, float& d2, float& d3,
    uint32_t a0, uint32_t a1, uint32_t a2, uint32_t a3,
    uint32_t b0, uint32_t b1)
{
    asm volatile(
        "mma.sync.aligned.m16n8k16.row.col.f32.bf16.bf16.f32 "
        "{%0,%1,%2,%3},{%4,%5,%6,%7},{%8,%9},{%0,%1,%2,%3};"
        : "+f"(d0), "+f"(d1), "+f"(d2), "+f"(d3)
        : "r"(a0), "r"(a1), "r"(a2), "r"(a3), "r"(b0), "r"(b1));
}
__device__ __forceinline__ void cpa16(uint32_t dst, const void* src){
    asm volatile("cp.async.cg.shared.global [%0], [%1], 16;"
                 :: "r"(dst), "l"(src));
}
__device__ __forceinline__ void ldsm_x4(uint32_t& a0, uint32_t& a1,
                                        uint32_t& a2, uint32_t& a3, uint32_t addr){
    asm volatile("ldmatrix.sync.aligned.m8n8.x4.shared.b16 {%0,%1,%2,%3}, [%4];"
                 : "=r"(a0), "=r"(a1), "=r"(a2), "=r"(a3) : "r"(addr));
}

// flash smem layout (128-j staging tiles)
#define OFF_QS    0                  // f32 idx, 8*72
#define OFF_KS    576                // [wg][par] K bufs: 128 rows * 12 f32
#define KBUF_F    1536
#define VS_BYTE   26880              // ((576 + 4*1536)*4)
#define VBUF_B    17408              // 64 rows * 272B
#define OFF_L     24128              // f32 idx, [2][64]
#define SM_FLTS   24256              // 97024 B (dynamic)
#define OFF_OFIN  6720               // f32 idx, 64*68 (reuses V region)
#define OFF_OST   11072              // f32 idx, 64*68

#define LOG2E  1.4426950408889634f
#define SHIFT2 (-17.312340490667561f)   // -12 * log2(e)
#define ONESBF 0x3F803F80u

// ---------------- kernel 1: fused 1x1 convs, c-quad vectorized weights ---------
__global__ __launch_bounds__(256) void qkv_kernel(
    const float* __restrict__ x,
    const float* __restrict__ qw, const float* __restrict__ qb,
    const float* __restrict__ kw, const float* __restrict__ kb,
    const float* __restrict__ vw, const float* __restrict__ vb,
    const float* __restrict__ w1, const float* __restrict__ b1)
{
    __shared__ float Ws[96*68];     // pitch 68: vec4-aligned w rows
    __shared__ float bs[96];
    __shared__ float xs[64*64];

    const int b  = blockIdx.y;
    const int n0 = blockIdx.x * 64;
    const int t  = threadIdx.x;

    for (int i = t; i < 512;  i += 256) Ws[( 0 + (i>>6))*68 + (i&63)] = qw[i];
    for (int i = t; i < 512;  i += 256) Ws[( 8 + (i>>6))*68 + (i&63)] = kw[i];
    for (int i = t; i < 4096; i += 256) Ws[(16 + (i>>6))*68 + (i&63)] = vw[i];
    for (int i = t; i < 1024; i += 256) Ws[(80 + (i>>6))*68 + (i&63)] = w1[i];
    if (t < 96) {
        float bv;
        if      (t < 8)  bv = qb[t];
        else if (t < 16) bv = kb[t-8];
        else if (t < 80) bv = vb[t-16];
        else             bv = b1[t-80];
        bs[t] = bv;
    }
    #pragma unroll
    for (int kk = 0; kk < 4; kk++) {
        int idx4 = t + 256*kk;
        int c = idx4 >> 4, n4 = idx4 & 15;
        float4 v = *((const float4*)(x + ((size_t)b*CCH + c)*NN + n0) + n4);
        *((float4*)(xs + c*64) + n4) = v;
    }
    __syncthreads();

    const int ng  = t & 15;
    const int ocg = t >> 4;
    float acc[6][4];
    #pragma unroll
    for (int k = 0; k < 6; k++) {
        float bv = bs[ocg*6 + k];
        acc[k][0] = bv; acc[k][1] = bv; acc[k][2] = bv; acc[k][3] = bv;
    }
    #pragma unroll 4
    for (int cq = 0; cq < 64; cq += 4) {
        float4 xv0 = *(const float4*)(xs + (cq+0)*64 + ng*4);
        float4 xv1 = *(const float4*)(xs + (cq+1)*64 + ng*4);
        float4 xv2 = *(const float4*)(xs + (cq+2)*64 + ng*4);
        float4 xv3 = *(const float4*)(xs + (cq+3)*64 + ng*4);
        #pragma unroll
        for (int k = 0; k < 6; k++) {
            float4 wv = *(const float4*)(Ws + (ocg*6 + k)*68 + cq);
            acc[k][0] += wv.x*xv0.x + wv.y*xv1.x + wv.z*xv2.x + wv.w*xv3.x;
            acc[k][1] += wv.x*xv0.y + wv.y*xv1.y + wv.z*xv2.y + wv.w*xv3.y;
            acc[k][2] += wv.x*xv0.z + wv.y*xv1.z + wv.z*xv2.z + wv.w*xv3.z;
            acc[k][3] += wv.x*xv0.w + wv.y*xv1.w + wv.z*xv2.w + wv.w*xv3.w;
        }
    }
    const int gn = n0 + ng*4;
    #pragma unroll
    for (int k = 0; k < 6; k++) {
        int oc = ocg*6 + k;
        if (oc < 8) {
            float4 o = make_float4(to_tf32(acc[k][0]), to_tf32(acc[k][1]),
                                   to_tf32(acc[k][2]), to_tf32(acc[k][3]));
            *(float4*)(g_q + ((size_t)b*DQK + oc)*NN + gn) = o;
        } else if (oc < 16) {
            int d = oc - 8;
            #pragma unroll
            for (int u = 0; u < 4; u++)
                g_k[((size_t)b*NN + gn + u)*DQK + d] = to_tf32(acc[k][u]);
        } else if (oc < 80) {
            uint2 pk;
            pk.x = pack_bf16(acc[k][0], acc[k][1]);
            pk.y = pack_bf16(acc[k][2], acc[k][3]);
            *(uint2*)(g_v + ((size_t)b*CCH + oc - 16)*NN + gn) = pk;
        } else {
            size_t o = ((size_t)b*FCH + oc - 80)*NN + gn;
            float e0 = __expf(acc[k][0]), e1 = __expf(acc[k][1]);
            float e2 = __expf(acc[k][2]), e3 = __expf(acc[k][3]);
            *(float4*)(g_e  + o) = make_float4(e0, e1, e2, e3);
            *(float4*)(g_ev + o) = make_float4(e0*acc[k][0], e1*acc[k][1],
                                               e2*acc[k][2], e3*acc[k][3]);
        }
    }
}

// ---------------- kernel 2: softpool -------------------------------------------
__global__ void softpool_kernel()
{
    int idx = blockIdx.x*blockDim.x + threadIdx.x;
    if (idx >= BATCH*FCH*400) return;
    int ox = idx % 20, oy = (idx/20) % 20;
    int c  = (idx/400) % FCH, b = idx/(400*FCH);
    size_t base = ((size_t)b*FCH + c)*NN + (oy*3)*64 + ox*3;
    const float* se  = g_e  + base;
    const float* sev = g_ev + base;
    float num = 0.f, den = 0.f;
    #pragma unroll
    for (int ky = 0; ky < 7; ky++)
        #pragma unroll
        for (int kx = 0; kx < 7; kx++) {
            num += sev[ky*64 + kx];
            den += se [ky*64 + kx];
        }
    g_y2[idx] = num/den;
}

// ---------------- kernel 3: conv2 (redundant) -> conv3(4 oc) + sigmoid ---------
__global__ __launch_bounds__(256) void conv23_kernel(
    const float* __restrict__ w2, const float* __restrict__ b2,
    const float* __restrict__ w3, const float* __restrict__ b3)
{
    __shared__ float y2s[FCH*400];
    __shared__ float y3s[FCH*100];
    const int b  = blockIdx.x >> 4;
    const int og = blockIdx.x & 15;
    const int t  = threadIdx.x;

    for (int o = t; o < FCH*400; o += 256) y2s[o] = g_y2[(size_t)b*FCH*400 + o];
    __syncthreads();

    for (int o = t; o < FCH*100; o += 256) {
        int ox = o % 10, oy = (o/10) % 10, oc = o/100;
        float acc = b2[oc];
        for (int ic = 0; ic < FCH; ic++) {
            const float* src = y2s + ic*400;
            const float* wr  = w2 + (oc*FCH + ic)*9;
            #pragma unroll
            for (int ky = 0; ky < 3; ky++) {
                int iy = oy*2 - 1 + ky;
                if (iy < 0 || iy >= 20) continue;
                #pragma unroll
                for (int kx = 0; kx < 3; kx++) {
                    int ix = ox*2 - 1 + kx;
                    if (ix < 0 || ix >= 20) continue;
                    acc += wr[ky*3+kx] * src[iy*20 + ix];
                }
            }
        }
        y3s[o] = acc;
    }
    __syncthreads();

    for (int o = t; o < 400; o += 256) {
        int ox = o % 10, oy = (o/10) % 10;
        int oc = og*4 + o/100;
        float acc = b3[oc];
        for (int ic = 0; ic < FCH; ic++) {
            const float* src = y3s + ic*100;
            const float* wr  = w3 + (oc*FCH + ic)*9;
            #pragma unroll
            for (int ky = 0; ky < 3; ky++) {
                int iy = oy - 1 + ky;
                if (iy < 0 || iy >= 10) continue;
                #pragma unroll
                for (int kx = 0; kx < 3; kx++) {
                    int ix = ox - 1 + kx;
                    if (ix < 0 || ix >= 10) continue;
                    acc += wr[ky*3+kx] * src[iy*10 + ix];
                }
            }
        }
        g_y4[((size_t)b*CCH + oc)*100 + (o % 100)] = 1.f/(1.f + __expf(-acc));
    }
}

// ---------------- kernel 4: flash — 128-j staging, two 64-j halves per tile ----
__global__ __launch_bounds__(256, 2) void flash_tc_kernel(
    const float* __restrict__ x, const float* __restrict__ gamma_p,
    float* __restrict__ out)
{
    extern __shared__ __align__(16) float sm[];
    const int b  = blockIdx.y;
    const int i0 = blockIdx.x * 64;
    const int t  = threadIdx.x;
    const int wg = t >> 7;
    const int tg = t & 127;
    const int w4 = tg >> 5;
    const int lane = t & 31;
    const int r  = lane >> 2;
    const int q4 = lane & 3;
    const int bar = wg + 1;

    for (int kx = t; kx < 512; kx += 256) {
        int d = kx >> 6, i = kx & 63;
        sm[OFF_QS + d*72 + i] = g_q[((size_t)b*DQK + d)*NN + i0 + i];
    }

    // K cp.async: row tg of 128 (32B data in 48B pitch), 2 chunks per thread
    const float* ksrc = g_k + ((size_t)b*NN + wg*2048 + tg)*DQK;
    uint32_t kdst[2];
    #pragma unroll
    for (int p = 0; p < 2; p++)
        kdst[p] = (uint32_t)__cvta_generic_to_shared(
            sm + OFF_KS + (wg*2 + p)*KBUF_F + tg*12);

    // V cp.async (bf16, [c][128j] 256B data in 272B pitch): 8 chunks per thread
    const __nv_bfloat16* vsrc[8];
    uint32_t vdst[2][8];
    #pragma unroll
    for (int kk = 0; kk < 8; kk++) {
        int cc = tg + 128*kk;            // 1024 chunks
        int c = cc >> 4, jj = cc & 15;
        vsrc[kk] = g_v + ((size_t)b*CCH + c)*NN + wg*2048 + jj*8;
        #pragma unroll
        for (int p = 0; p < 2; p++)
            vdst[p][kk] = (uint32_t)__cvta_generic_to_shared(
                (char*)sm + VS_BYTE + (wg*2 + p)*VBUF_B + c*272 + jj*16);
    }

    // ldmatrix lane offsets
    const uint32_t vlm_off = (uint32_t)(((lane & 7) + ((lane >> 4) & 1)*8)*272
                                        + ((lane >> 3) & 1)*16);
    const uint32_t klm_off = (uint32_t)(((lane & 7) + ((lane >> 4) & 1)*8)*48
                                        + ((lane >> 3) & 1)*16);
    uint32_t vlm[2], klm[2];
    #pragma unroll
    for (int p = 0; p < 2; p++) {
        vlm[p] = (uint32_t)__cvta_generic_to_shared(
                     (char*)sm + VS_BYTE + (wg*2 + p)*VBUF_B) + vlm_off;
        klm[p] = (uint32_t)__cvta_generic_to_shared(
                     sm + OFF_KS + (wg*2 + p)*KBUF_F) + klm_off;
    }

    cpa16(kdst[0], ksrc);
    cpa16(kdst[0] + 16, ksrc + 4);
    #pragma unroll
    for (int kk = 0; kk < 8; kk++) cpa16(vdst[0][kk], vsrc[kk]);
    asm volatile("cp.async.commit_group;");

    __syncthreads();
    const uint32_t aq0 = __float_as_uint(sm[OFF_QS +  q4   *72 + 16*w4 + r    ]);
    const uint32_t aq1 = __float_as_uint(sm[OFF_QS +  q4   *72 + 16*w4 + r + 8]);
    const uint32_t aq2 = __float_as_uint(sm[OFF_QS + (q4+4)*72 + 16*w4 + r    ]);
    const uint32_t aq3 = __float_as_uint(sm[OFF_QS + (q4+4)*72 + 16*w4 + r + 8]);

    float Oa[8][4];
    #pragma unroll
    for (int nc = 0; nc < 8; nc++)
        #pragma unroll
        for (int u = 0; u < 4; u++) Oa[nc][u] = 0.f;
    float La[4] = {0.f, 0.f, 0.f, 0.f};
    int par = 0;

    for (int it = 0; it < 16; ++it) {
        asm volatile("bar.sync %0, 128;" :: "r"(bar));
        if (it + 1 < 16) {
            int off = (it + 1)*128;
            cpa16(kdst[par^1],      ksrc + (size_t)off*DQK);
            cpa16(kdst[par^1] + 16, ksrc + (size_t)off*DQK + 4);
            #pragma unroll
            for (int kk = 0; kk < 8; kk++) cpa16(vdst[par^1][kk], vsrc[kk] + off);
        }
        asm volatile("cp.async.commit_group;");
        asm volatile("cp.async.wait_group 1;");
        asm volatile("bar.sync %0, 128;" :: "r"(bar));

        #pragma unroll
        for (int h = 0; h < 2; h++) {
            const uint32_t kb = klm[par] + h*3072;    // 64 rows * 48B
            const uint32_t vb = vlm[par] + h*128;     // 64 j * 2B within rows

            // ---- S = Q*K (tf32); K B-frags via ldmatrix on [j][d]
            float P[8][4];
            #pragma unroll
            for (int g = 0; g < 4; g++) {
                uint32_t b0a, b1a, b0b, b1b;
                ldsm_x4(b0a, b1a, b0b, b1b, kb + g*768);
                P[2*g  ][0] = P[2*g  ][1] = P[2*g  ][2] = P[2*g  ][3] = 0.f;
                P[2*g+1][0] = P[2*g+1][1] = P[2*g+1][2] = P[2*g+1][3] = 0.f;
                mma_tf32(P[2*g  ][0], P[2*g  ][1], P[2*g  ][2], P[2*g  ][3],
                         aq0, aq1, aq2, aq3, b0a, b1a);
                mma_tf32(P[2*g+1][0], P[2*g+1][1], P[2*g+1][2], P[2*g+1][3],
                         aq0, aq1, aq2, aq3, b0b, b1b);
            }
            // ---- P = exp(S - 12), pack bf16x2
            uint32_t Pbl[8], Pbh[8];
            #pragma unroll
            for (int t8 = 0; t8 < 8; t8++) {
                float p0 = ex2f(fmaf(P[t8][0], LOG2E, SHIFT2));
                float p1 = ex2f(fmaf(P[t8][1], LOG2E, SHIFT2));
                float p2 = ex2f(fmaf(P[t8][2], LOG2E, SHIFT2));
                float p3 = ex2f(fmaf(P[t8][3], LOG2E, SHIFT2));
                Pbl[t8] = pack_bf16(p0, p1);
                Pbh[t8] = pack_bf16(p2, p3);
            }
            // ---- O += P·V ; l += P·1
            #pragma unroll
            for (int kt = 0; kt < 4; kt++) {
                uint32_t a0 = Pbl[2*kt],   a1 = Pbh[2*kt];
                uint32_t a2 = Pbl[2*kt+1], a3 = Pbh[2*kt+1];
                mma_bf16(La[0], La[1], La[2], La[3],
                         a0, a1, a2, a3, ONESBF, ONESBF);
                #pragma unroll
                for (int ncp = 0; ncp < 4; ncp++) {
                    uint32_t b0, b1, b2, b3;
                    ldsm_x4(b0, b1, b2, b3, vb + ncp*4352 + kt*32);
                    mma_bf16(Oa[2*ncp][0], Oa[2*ncp][1],
                             Oa[2*ncp][2], Oa[2*ncp][3],
                             a0, a1, a2, a3, b0, b1);
                    mma_bf16(Oa[2*ncp+1][0], Oa[2*ncp+1][1],
                             Oa[2*ncp+1][2], Oa[2*ncp+1][3],
                             a0, a1, a2, a3, b2, b3);
                }
            }
        }
        par ^= 1;
    }

    // ---- stage l and group-1 O -------------------------------------------------
    __syncthreads();
    if (q4 == 0) {
        sm[OFF_L + wg*64 + 16*w4 + r    ] = La[0];
        sm[OFF_L + wg*64 + 16*w4 + r + 8] = La[2];
    }
    if (wg == 1) {
        #pragma unroll
        for (int nc = 0; nc < 8; nc++)
            #pragma unroll
            for (int u = 0; u < 4; u++) {
                int c  = nc*8 + 2*q4 + (u & 1);
                int il = 16*w4 + r + 8*(u >> 1);
                sm[OFF_OST + c*68 + il] = Oa[nc][u];
            }
    }
    __syncthreads();

    // ---- group 0 merges: O = (O0 + O1) / (l0 + l1) ----------------------------
    if (wg == 0) {
        int iqa = 16*w4 + r;
        float inv0 = 1.f / (sm[OFF_L + iqa    ] + sm[OFF_L + 64 + iqa    ]);
        float inv1 = 1.f / (sm[OFF_L + iqa + 8] + sm[OFF_L + 64 + iqa + 8]);
        #pragma unroll
        for (int nc = 0; nc < 8; nc++)
            #pragma unroll
            for (int u = 0; u < 4; u++) {
                int c  = nc*8 + 2*q4 + (u & 1);
                int il = 16*w4 + r + 8*(u >> 1);
                sm[OFF_OFIN + c*68 + il] =
                    (Oa[nc][u] + sm[OFF_OST + c*68 + il]) * ((u >> 1) ? inv1 : inv0);
            }
    }
    __syncthreads();

    // ---- epilogue --------------------------------------------------------------
    const float gam = gamma_p[0];
    const int h = blockIdx.x;
    float sy = (h + 0.5f)*0.15625f - 0.5f;
    int   y0 = (int)floorf(sy);
    float fy = sy - (float)y0;
    int   y0c = max(y0, 0), y1c = min(y0 + 1, 9);

    #pragma unroll
    for (int kk = 0; kk < 4; kk++) {
        int idx4 = t + 256*kk;
        int c = idx4 >> 4, k4 = (idx4 & 15)*4;
        const float* yr0 = g_y4 + ((size_t)b*CCH + c)*100 + y0c*10;
        const float* yr1 = g_y4 + ((size_t)b*CCH + c)*100 + y1c*10;
        size_t off = ((size_t)b*CCH + c)*NN + i0 + k4;
        float4 xv = *(const float4*)(x + off);
        float4 g4 = *(const float4*)(x + (size_t)b*CCH*NN + i0 + k4);
        float xa[4] = {xv.x, xv.y, xv.z, xv.w};
        float ga[4] = {g4.x, g4.y, g4.z, g4.w};
        float res[4];
        #pragma unroll
        for (int u = 0; u < 4; u++) {
            int wpix = k4 + u;
            float sx = (wpix + 0.5f)*0.15625f - 0.5f;
            int   x0i = (int)floorf(sx);
            float fx = sx - (float)x0i;
            int   x0c = max(x0i, 0), x1c = min(x0i + 1, 9);
            float v00 = yr0[x0c], v01 = yr0[x1c];
            float v10 = yr1[x0c], v11 = yr1[x1c];
            float wv = (1.f-fy)*((1.f-fx)*v00 + fx*v01)
                     +       fy*((1.f-fx)*v10 + fx*v11);
            float gate = 1.f/(1.f + __expf(-ga[u]));
            res[u] = gam*sm[OFF_OFIN + c*68 + k4 + u] + xa[u]*(2.f + wv*gate);
        }
        *(float4*)(out + off) = make_float4(res[0], res[1], res[2], res[3]);
    }
}

// ---------------- launch -------------------------------------------------------
extern "C" void kernel_launch(void* const* d_in, const int* in_sizes, int n_in,
                              void* d_out, int out_size)
{
    const float* x     = (const float*)d_in[0];
    const float* qw    = (const float*)d_in[1];
    const float* qb    = (const float*)d_in[2];
    const float* kw    = (const float*)d_in[3];
    const float* kb    = (const float*)d_in[4];
    const float* vw    = (const float*)d_in[5];
    const float* vb    = (const float*)d_in[6];
    const float* gamma = (const float*)d_in[7];
    const float* w1    = (const float*)d_in[8];
    const float* b1    = (const float*)d_in[9];
    const float* w2    = (const float*)d_in[10];
    const float* b2    = (const float*)d_in[11];
    const float* w3    = (const float*)d_in[12];
    const float* b3    = (const float*)d_in[13];
    float* out = (float*)d_out;

    const int smem = SM_FLTS * 4;   // 97024 B
    cudaFuncSetAttribute(flash_tc_kernel,
                         cudaFuncAttributeMaxDynamicSharedMemorySize, smem);

    qkv_kernel<<<dim3(64, BATCH), 256>>>(x, qw, qb, kw, kb, vw, vb, w1, b1);
    softpool_kernel<<<100, 256>>>();
    conv23_kernel<<<64, 256>>>(w2, b2, w3, b3);
    flash_tc_kernel<<<dim3(64, BATCH), 256, smem>>>(x, gamma, out);
}

// round 12
// speedup vs baseline: 1.0711x; 1.0711x over previous
#include <cuda_runtime.h>
#include <cuda_bf16.h>
#include <math.h>
#include <stdint.h>

#define BATCH 4
#define CCH   64
#define NN    4096
#define DQK   8
#define FCH   16

// ---------------- scratch ------------------------------------------------------
__device__ float g_q [BATCH*DQK*NN];            // tf32 bits, [b][d][i]
__device__ float g_k [BATCH*NN*DQK];            // tf32 bits, [b][j][d]
__device__ __nv_bfloat16 g_v [BATCH*CCH*NN];    // bf16 [b][c][j]
__device__ float g_e [BATCH*FCH*NN];
__device__ float g_ev[BATCH*FCH*NN];
__device__ float g_y2[BATCH*FCH*400];
__device__ float g_y4[BATCH*CCH*100];

__device__ __forceinline__ float to_tf32(float x){
    uint32_t r;
    asm("cvt.rna.tf32.f32 %0, %1;" : "=r"(r) : "f"(x));
    return __uint_as_float(r);
}
__device__ __forceinline__ uint32_t pack_bf16(float lo, float hi){
    uint32_t d;
    asm("cvt.rn.bf16x2.f32 %0, %1, %2;" : "=r"(d) : "f"(hi), "f"(lo));
    return d;
}
__device__ __forceinline__ float ex2f(float x){
    float r;
    asm("ex2.approx.f32 %0, %1;" : "=f"(r) : "f"(x));
    return r;
}
__device__ __forceinline__ void mma_tf32(
    float& d0, float& d1, float& d2, float& d3,
    uint32_t a0, uint32_t a1, uint32_t a2, uint32_t a3,
    uint32_t b0, uint32_t b1)
{
    asm volatile(
        "mma.sync.aligned.m16n8k8.row.col.f32.tf32.tf32.f32 "
        "{%0,%1,%2,%3},{%4,%5,%6,%7},{%8,%9},{%0,%1,%2,%3};"
        : "+f"(d0), "+f"(d1), "+f"(d2), "+f"(d3)
        : "r"(a0), "r"(a1), "r"(a2), "r"(a3), "r"(b0), "r"(b1));
}
__device__ __forceinline__ void mma_bf16(
    float& d0, float& d1, float& d2, float& d3,
    uint32_t a0, uint32_t a1, uint32_t a2, uint32_t a3,
    uint32_t b0, uint32_t b1)
{
    asm volatile(
        "mma.sync.aligned.m16n8k16.row.col.f32.bf16.bf16.f32 "
        "{%0,%1,%2,%3},{%4,%5,%6,%7},{%8,%9},{%0,%1,%2,%3};"
        : "+f"(d0), "+f"(d1), "+f"(d2), "+f"(d3)
        : "r"(a0), "r"(a1), "r"(a2), "r"(a3), "r"(b0), "r"(b1));
}
__device__ __forceinline__ void cpa16(uint32_t dst, const void* src){
    asm volatile("cp.async.cg.shared.global [%0], [%1], 16;"
                 :: "r"(dst), "l"(src));
}
__device__ __forceinline__ void ldsm_x4(uint32_t& a0, uint32_t& a1,
                                        uint32_t& a2, uint32_t& a3, uint32_t addr){
    asm volatile("ldmatrix.sync.aligned.m8n8.x4.shared.b16 {%0,%1,%2,%3}, [%4];"
                 : "=r"(a0), "=r"(a1), "=r"(a2), "=r"(a3) : "r"(addr));
}

// flash smem layout (64-j tiles, R10 structure)
#define OFF_QS    0                  // f32 idx, 8*72
#define OFF_KS    576                // [wg][par] K bufs: 64 rows * 12 f32 (48B pad)
#define KBUF_F    768
#define VS_BYTE   14592              // byte offset of V region ((576+3072)*4)
#define VBUF_B    9216               // 64 rows * 144B
#define OFF_L     12864              // f32 idx, [2][64]
#define SM_FLTS   12992              // 51968 B (dynamic)
#define OFF_OFIN  3648               // f32 idx, 64*68 (reuses V region)
#define OFF_OST   8000               // f32 idx, 64*68

#define LOG2E  1.4426950408889634f
#define SHIFT2 (-17.312340490667561f)   // -12 * log2(e)
#define ONESBF 0x3F803F80u

// ---------------- kernel 1: fused 1x1 convs, c-quad vectorized weights ---------
__global__ __launch_bounds__(256) void qkv_kernel(
    const float* __restrict__ x,
    const float* __restrict__ qw, const float* __restrict__ qb,
    const float* __restrict__ kw, const float* __restrict__ kb,
    const float* __restrict__ vw, const float* __restrict__ vb,
    const float* __restrict__ w1, const float* __restrict__ b1)
{
    __shared__ float Ws[96*68];
    __shared__ float bs[96];
    __shared__ float xs[64*64];

    const int b  = blockIdx.y;
    const int n0 = blockIdx.x * 64;
    const int t  = threadIdx.x;

    for (int i = t; i < 512;  i += 256) Ws[( 0 + (i>>6))*68 + (i&63)] = qw[i];
    for (int i = t; i < 512;  i += 256) Ws[( 8 + (i>>6))*68 + (i&63)] = kw[i];
    for (int i = t; i < 4096; i += 256) Ws[(16 + (i>>6))*68 + (i&63)] = vw[i];
    for (int i = t; i < 1024; i += 256) Ws[(80 + (i>>6))*68 + (i&63)] = w1[i];
    if (t < 96) {
        float bv;
        if      (t < 8)  bv = qb[t];
        else if (t < 16) bv = kb[t-8];
        else if (t < 80) bv = vb[t-16];
        else             bv = b1[t-80];
        bs[t] = bv;
    }
    #pragma unroll
    for (int kk = 0; kk < 4; kk++) {
        int idx4 = t + 256*kk;
        int c = idx4 >> 4, n4 = idx4 & 15;
        float4 v = *((const float4*)(x + ((size_t)b*CCH + c)*NN + n0) + n4);
        *((float4*)(xs + c*64) + n4) = v;
    }
    __syncthreads();

    const int ng  = t & 15;
    const int ocg = t >> 4;
    float acc[6][4];
    #pragma unroll
    for (int k = 0; k < 6; k++) {
        float bv = bs[ocg*6 + k];
        acc[k][0] = bv; acc[k][1] = bv; acc[k][2] = bv; acc[k][3] = bv;
    }
    #pragma unroll 4
    for (int cq = 0; cq < 64; cq += 4) {
        float4 xv0 = *(const float4*)(xs + (cq+0)*64 + ng*4);
        float4 xv1 = *(const float4*)(xs + (cq+1)*64 + ng*4);
        float4 xv2 = *(const float4*)(xs + (cq+2)*64 + ng*4);
        float4 xv3 = *(const float4*)(xs + (cq+3)*64 + ng*4);
        #pragma unroll
        for (int k = 0; k < 6; k++) {
            float4 wv = *(const float4*)(Ws + (ocg*6 + k)*68 + cq);
            acc[k][0] += wv.x*xv0.x + wv.y*xv1.x + wv.z*xv2.x + wv.w*xv3.x;
            acc[k][1] += wv.x*xv0.y + wv.y*xv1.y + wv.z*xv2.y + wv.w*xv3.y;
            acc[k][2] += wv.x*xv0.z + wv.y*xv1.z + wv.z*xv2.z + wv.w*xv3.z;
            acc[k][3] += wv.x*xv0.w + wv.y*xv1.w + wv.z*xv2.w + wv.w*xv3.w;
        }
    }
    const int gn = n0 + ng*4;
    #pragma unroll
    for (int k = 0; k < 6; k++) {
        int oc = ocg*6 + k;
        if (oc < 8) {
            float4 o = make_float4(to_tf32(acc[k][0]), to_tf32(acc[k][1]),
                                   to_tf32(acc[k][2]), to_tf32(acc[k][3]));
            *(float4*)(g_q + ((size_t)b*DQK + oc)*NN + gn) = o;
        } else if (oc < 16) {
            int d = oc - 8;
            #pragma unroll
            for (int u = 0; u < 4; u++)
                g_k[((size_t)b*NN + gn + u)*DQK + d] = to_tf32(acc[k][u]);
        } else if (oc < 80) {
            uint2 pk;
            pk.x = pack_bf16(acc[k][0], acc[k][1]);
            pk.y = pack_bf16(acc[k][2], acc[k][3]);
            *(uint2*)(g_v + ((size_t)b*CCH + oc - 16)*NN + gn) = pk;
        } else {
            size_t o = ((size_t)b*FCH + oc - 80)*NN + gn;
            float e0 = __expf(acc[k][0]), e1 = __expf(acc[k][1]);
            float e2 = __expf(acc[k][2]), e3 = __expf(acc[k][3]);
            *(float4*)(g_e  + o) = make_float4(e0, e1, e2, e3);
            *(float4*)(g_ev + o) = make_float4(e0*acc[k][0], e1*acc[k][1],
                                               e2*acc[k][2], e3*acc[k][3]);
        }
    }
}

// ---------------- kernel 2: softpool -------------------------------------------
__global__ void softpool_kernel()
{
    int idx = blockIdx.x*blockDim.x + threadIdx.x;
    if (idx >= BATCH*FCH*400) return;
    int ox = idx % 20, oy = (idx/20) % 20;
    int c  = (idx/400) % FCH, b = idx/(400*FCH);
    size_t base = ((size_t)b*FCH + c)*NN + (oy*3)*64 + ox*3;
    const float* se  = g_e  + base;
    const float* sev = g_ev + base;
    float num = 0.f, den = 0.f;
    #pragma unroll
    for (int ky = 0; ky < 7; ky++)
        #pragma unroll
        for (int kx = 0; kx < 7; kx++) {
            num += sev[ky*64 + kx];
            den += se [ky*64 + kx];
        }
    g_y2[idx] = num/den;
}

// ---------------- kernel 3: conv2 (redundant) -> conv3(4 oc) + sigmoid ---------
__global__ __launch_bounds__(256) void conv23_kernel(
    const float* __restrict__ w2, const float* __restrict__ b2,
    const float* __restrict__ w3, const float* __restrict__ b3)
{
    __shared__ float y2s[FCH*400];
    __shared__ float y3s[FCH*100];
    const int b  = blockIdx.x >> 4;
    const int og = blockIdx.x & 15;
    const int t  = threadIdx.x;

    for (int o = t; o < FCH*400; o += 256) y2s[o] = g_y2[(size_t)b*FCH*400 + o];
    __syncthreads();

    for (int o = t; o < FCH*100; o += 256) {
        int ox = o % 10, oy = (o/10) % 10, oc = o/100;
        float acc = b2[oc];
        for (int ic = 0; ic < FCH; ic++) {
            const float* src = y2s + ic*400;
            const float* wr  = w2 + (oc*FCH + ic)*9;
            #pragma unroll
            for (int ky = 0; ky < 3; ky++) {
                int iy = oy*2 - 1 + ky;
                if (iy < 0 || iy >= 20) continue;
                #pragma unroll
                for (int kx = 0; kx < 3; kx++) {
                    int ix = ox*2 - 1 + kx;
                    if (ix < 0 || ix >= 20) continue;
                    acc += wr[ky*3+kx] * src[iy*20 + ix];
                }
            }
        }
        y3s[o] = acc;
    }
    __syncthreads();

    for (int o = t; o < 400; o += 256) {
        int ox = o % 10, oy = (o/10) % 10;
        int oc = og*4 + o/100;
        float acc = b3[oc];
        for (int ic = 0; ic < FCH; ic++) {
            const float* src = y3s + ic*100;
            const float* wr  = w3 + (oc*FCH + ic)*9;
            #pragma unroll
            for (int ky = 0; ky < 3; ky++) {
                int iy = oy - 1 + ky;
                if (iy < 0 || iy >= 10) continue;
                #pragma unroll
                for (int kx = 0; kx < 3; kx++) {
                    int ix = ox - 1 + kx;
                    if (ix < 0 || ix >= 10) continue;
                    acc += wr[ky*3+kx] * src[iy*10 + ix];
                }
            }
        }
        g_y4[((size_t)b*CCH + oc)*100 + (o % 100)] = 1.f/(1.f + __expf(-acc));
    }
}

// ---------------- kernel 4: flash — interleaved exp/mma (pipe overlap) ---------
__global__ __launch_bounds__(256, 2) void flash_tc_kernel(
    const float* __restrict__ x, const float* __restrict__ gamma_p,
    float* __restrict__ out)
{
    extern __shared__ __align__(16) float sm[];
    const int b  = blockIdx.y;
    const int i0 = blockIdx.x * 64;
    const int t  = threadIdx.x;
    const int wg = t >> 7;
    const int tg = t & 127;
    const int w4 = tg >> 5;
    const int lane = t & 31;
    const int r  = lane >> 2;
    const int q4 = lane & 3;
    const int bar = wg + 1;

    for (int kx = t; kx < 512; kx += 256) {
        int d = kx >> 6, i = kx & 63;
        sm[OFF_QS + d*72 + i] = g_q[((size_t)b*DQK + d)*NN + i0 + i];
    }

    // K cp.async: [j][d] rows (32B data in 48B pitch), 128 x 16B chunks
    const int krow = tg >> 1, khalf = tg & 1;
    const float* ksrc = g_k + ((size_t)b*NN + wg*2048 + krow)*DQK + khalf*4;
    uint32_t kdst[2];
    #pragma unroll
    for (int p = 0; p < 2; p++)
        kdst[p] = (uint32_t)__cvta_generic_to_shared(
            sm + OFF_KS + (wg*2 + p)*KBUF_F + krow*12 + khalf*4);

    // V cp.async (bf16, [c][j] pitch 144B): 4 x 16B chunks per thread
    const __nv_bfloat16* vsrc[4];
    uint32_t vdst[2][4];
    #pragma unroll
    for (int kk = 0; kk < 4; kk++) {
        int cc = tg + 128*kk;
        int c = cc >> 3, jj = cc & 7;
        vsrc[kk] = g_v + ((size_t)b*CCH + c)*NN + wg*2048 + jj*8;
        #pragma unroll
        for (int p = 0; p < 2; p++)
            vdst[p][kk] = (uint32_t)__cvta_generic_to_shared(
                (char*)sm + VS_BYTE + (wg*2 + p)*VBUF_B + c*144 + jj*16);
    }

    // ldmatrix lane offsets
    const uint32_t vlm_off = (uint32_t)(((lane & 7) + ((lane >> 4) & 1)*8)*144
                                        + ((lane >> 3) & 1)*16);
    const uint32_t klm_off = (uint32_t)(((lane & 7) + ((lane >> 4) & 1)*8)*48
                                        + ((lane >> 3) & 1)*16);
    uint32_t vlm[2], klm[2];
    #pragma unroll
    for (int p = 0; p < 2; p++) {
        vlm[p] = (uint32_t)__cvta_generic_to_shared(
                     (char*)sm + VS_BYTE + (wg*2 + p)*VBUF_B) + vlm_off;
        klm[p] = (uint32_t)__cvta_generic_to_shared(
                     sm + OFF_KS + (wg*2 + p)*KBUF_F) + klm_off;
    }

    cpa16(kdst[0], ksrc);
    #pragma unroll
    for (int kk = 0; kk < 4; kk++) cpa16(vdst[0][kk], vsrc[kk]);
    asm volatile("cp.async.commit_group;");

    __syncthreads();
    const uint32_t aq0 = __float_as_uint(sm[OFF_QS +  q4   *72 + 16*w4 + r    ]);
    const uint32_t aq1 = __float_as_uint(sm[OFF_QS +  q4   *72 + 16*w4 + r + 8]);
    const uint32_t aq2 = __float_as_uint(sm[OFF_QS + (q4+4)*72 + 16*w4 + r    ]);
    const uint32_t aq3 = __float_as_uint(sm[OFF_QS + (q4+4)*72 + 16*w4 + r + 8]);

    float Oa[8][4];
    #pragma unroll
    for (int nc = 0; nc < 8; nc++)
        #pragma unroll
        for (int u = 0; u < 4; u++) Oa[nc][u] = 0.f;
    float La[4] = {0.f, 0.f, 0.f, 0.f};
    int par = 0;

    for (int it = 0; it < 32; ++it) {
        asm volatile("bar.sync %0, 128;" :: "r"(bar));
        if (it + 1 < 32) {
            int off = (it + 1)*64;
            cpa16(kdst[par^1], ksrc + (size_t)off*DQK);
            #pragma unroll
            for (int kk = 0; kk < 4; kk++) cpa16(vdst[par^1][kk], vsrc[kk] + off);
        }
        asm volatile("cp.async.commit_group;");
        asm volatile("cp.async.wait_group 1;");
        asm volatile("bar.sync %0, 128;" :: "r"(bar));

        const uint32_t kb = klm[par];
        const uint32_t vb = vlm[par];

        // ---- S = Q*K (tf32); K B-frags via ldmatrix on [j][d]
        float P[8][4];
        #pragma unroll
        for (int g = 0; g < 4; g++) {
            uint32_t b0a, b1a, b0b, b1b;
            ldsm_x4(b0a, b1a, b0b, b1b, kb + g*768);
            P[2*g  ][0] = P[2*g  ][1] = P[2*g  ][2] = P[2*g  ][3] = 0.f;
            P[2*g+1][0] = P[2*g+1][1] = P[2*g+1][2] = P[2*g+1][3] = 0.f;
            mma_tf32(P[2*g  ][0], P[2*g  ][1], P[2*g  ][2], P[2*g  ][3],
                     aq0, aq1, aq2, aq3, b0a, b1a);
            mma_tf32(P[2*g+1][0], P[2*g+1][1], P[2*g+1][2], P[2*g+1][3],
                     aq0, aq1, aq2, aq3, b0b, b1b);
        }

        // ---- interleaved: per kt, exp/pack just the needed P pair, then mma ----
        #pragma unroll
        for (int kt = 0; kt < 4; kt++) {
            float e0 = ex2f(fmaf(P[2*kt  ][0], LOG2E, SHIFT2));
            float e1 = ex2f(fmaf(P[2*kt  ][1], LOG2E, SHIFT2));
            float e2 = ex2f(fmaf(P[2*kt  ][2], LOG2E, SHIFT2));
            float e3 = ex2f(fmaf(P[2*kt  ][3], LOG2E, SHIFT2));
            float f0 = ex2f(fmaf(P[2*kt+1][0], LOG2E, SHIFT2));
            float f1 = ex2f(fmaf(P[2*kt+1][1], LOG2E, SHIFT2));
            float f2 = ex2f(fmaf(P[2*kt+1][2], LOG2E, SHIFT2));
            float f3 = ex2f(fmaf(P[2*kt+1][3], LOG2E, SHIFT2));
            uint32_t a0 = pack_bf16(e0, e1);
            uint32_t a1 = pack_bf16(e2, e3);
            uint32_t a2 = pack_bf16(f0, f1);
            uint32_t a3 = pack_bf16(f2, f3);
            mma_bf16(La[0], La[1], La[2], La[3],
                     a0, a1, a2, a3, ONESBF, ONESBF);
            #pragma unroll
            for (int ncp = 0; ncp < 4; ncp++) {
                uint32_t b0, b1, b2, b3;
                ldsm_x4(b0, b1, b2, b3, vb + ncp*2304 + kt*32);
                mma_bf16(Oa[2*ncp][0], Oa[2*ncp][1], Oa[2*ncp][2], Oa[2*ncp][3],
                         a0, a1, a2, a3, b0, b1);
                mma_bf16(Oa[2*ncp+1][0], Oa[2*ncp+1][1],
                         Oa[2*ncp+1][2], Oa[2*ncp+1][3],
                         a0, a1, a2, a3, b2, b3);
            }
        }
        par ^= 1;
    }

    // ---- stage l and group-1 O -------------------------------------------------
    __syncthreads();
    if (q4 == 0) {
        sm[OFF_L + wg*64 + 16*w4 + r    ] = La[0];
        sm[OFF_L + wg*64 + 16*w4 + r + 8] = La[2];
    }
    if (wg == 1) {
        #pragma unroll
        for (int nc = 0; nc < 8; nc++)
            #pragma unroll
            for (int u = 0; u < 4; u++) {
                int c  = nc*8 + 2*q4 + (u & 1);
                int il = 16*w4 + r + 8*(u >> 1);
                sm[OFF_OST + c*68 + il] = Oa[nc][u];
            }
    }
    __syncthreads();

    // ---- group 0 merges: O = (O0 + O1) / (l0 + l1) ----------------------------
    if (wg == 0) {
        int iqa = 16*w4 + r;
        float inv0 = 1.f / (sm[OFF_L + iqa    ] + sm[OFF_L + 64 + iqa    ]);
        float inv1 = 1.f / (sm[OFF_L + iqa + 8] + sm[OFF_L + 64 + iqa + 8]);
        #pragma unroll
        for (int nc = 0; nc < 8; nc++)
            #pragma unroll
            for (int u = 0; u < 4; u++) {
                int c  = nc*8 + 2*q4 + (u & 1);
                int il = 16*w4 + r + 8*(u >> 1);
                sm[OFF_OFIN + c*68 + il] =
                    (Oa[nc][u] + sm[OFF_OST + c*68 + il]) * ((u >> 1) ? inv1 : inv0);
            }
    }
    __syncthreads();

    // ---- epilogue --------------------------------------------------------------
    const float gam = gamma_p[0];
    const int h = blockIdx.x;
    float sy = (h + 0.5f)*0.15625f - 0.5f;
    int   y0 = (int)floorf(sy);
    float fy = sy - (float)y0;
    int   y0c = max(y0, 0), y1c = min(y0 + 1, 9);

    #pragma unroll
    for (int kk = 0; kk < 4; kk++) {
        int idx4 = t + 256*kk;
        int c = idx4 >> 4, k4 = (idx4 & 15)*4;
        const float* yr0 = g_y4 + ((size_t)b*CCH + c)*100 + y0c*10;
        const float* yr1 = g_y4 + ((size_t)b*CCH + c)*100 + y1c*10;
        size_t off = ((size_t)b*CCH + c)*NN + i0 + k4;
        float4 xv = *(const float4*)(x + off);
        float4 g4 = *(const float4*)(x + (size_t)b*CCH*NN + i0 + k4);
        float xa[4] = {xv.x, xv.y, xv.z, xv.w};
        float ga[4] = {g4.x, g4.y, g4.z, g4.w};
        float res[4];
        #pragma unroll
        for (int u = 0; u < 4; u++) {
            int wpix = k4 + u;
            float sx = (wpix + 0.5f)*0.15625f - 0.5f;
            int   x0i = (int)floorf(sx);
            float fx = sx - (float)x0i;
            int   x0c = max(x0i, 0), x1c = min(x0i + 1, 9);
            float v00 = yr0[x0c], v01 = yr0[x1c];
            float v10 = yr1[x0c], v11 = yr1[x1c];
            float wv = (1.f-fy)*((1.f-fx)*v00 + fx*v01)
                     +       fy*((1.f-fx)*v10 + fx*v11);
            float gate = 1.f/(1.f + __expf(-ga[u]));
            res[u] = gam*sm[OFF_OFIN + c*68 + k4 + u] + xa[u]*(2.f + wv*gate);
        }
        *(float4*)(out + off) = make_float4(res[0], res[1], res[2], res[3]);
    }
}

// ---------------- launch -------------------------------------------------------
extern "C" void kernel_launch(void* const* d_in, const int* in_sizes, int n_in,
                              void* d_out, int out_size)
{
    const float* x     = (const float*)d_in[0];
    const float* qw    = (const float*)d_in[1];
    const float* qb    = (const float*)d_in[2];
    const float* kw    = (const float*)d_in[3];
    const float* kb    = (const float*)d_in[4];
    const float* vw    = (const float*)d_in[5];
    const float* vb    = (const float*)d_in[6];
    const float* gamma = (const float*)d_in[7];
    const float* w1    = (const float*)d_in[8];
    const float* b1    = (const float*)d_in[9];
    const float* w2    = (const float*)d_in[10];
    const float* b2    = (const float*)d_in[11];
    const float* w3    = (const float*)d_in[12];
    const float* b3    = (const float*)d_in[13];
    float* out = (float*)d_out;

    const int smem = SM_FLTS * 4;   // 51968 B
    cudaFuncSetAttribute(flash_tc_kernel,
                         cudaFuncAttributeMaxDynamicSharedMemorySize, smem);

    qkv_kernel<<<dim3(64, BATCH), 256>>>(x, qw, qb, kw, kb, vw, vb, w1, b1);
    softpool_kernel<<<100, 256>>>();
    conv23_kernel<<<64, 256>>>(w2, b2, w3, b3);
    flash_tc_kernel<<<dim3(64, BATCH), 256, smem>>>(x, gamma, out);
}

// round 13
// speedup vs baseline: 1.1038x; 1.0305x over previous
#include <cuda_runtime.h>
#include <cuda_bf16.h>
#include <math.h>
#include <stdint.h>

#define BATCH 4
#define CCH   64
#define NN    4096
#define DQK   8
#define FCH   16

// ---------------- scratch ------------------------------------------------------
__device__ float g_q [BATCH*DQK*NN];            // tf32 bits, [b][d][i]
__device__ float g_k [BATCH*NN*DQK];            // tf32 bits, [b][j][d]
__device__ __nv_bfloat16 g_v [BATCH*CCH*NN];    // bf16 [b][c][j]
__device__ float g_e [BATCH*FCH*NN];
__device__ float g_ev[BATCH*FCH*NN];
__device__ float g_y2[BATCH*FCH*400];
__device__ float g_y4[BATCH*CCH*100];

__device__ __forceinline__ float to_tf32(float x){
    uint32_t r;
    asm("cvt.rna.tf32.f32 %0, %1;" : "=r"(r) : "f"(x));
    return __uint_as_float(r);
}
__device__ __forceinline__ uint32_t pack_bf16(float lo, float hi){
    uint32_t d;
    asm("cvt.rn.bf16x2.f32 %0, %1, %2;" : "=r"(d) : "f"(hi), "f"(lo));
    return d;
}
__device__ __forceinline__ float ex2f(float x){
    float r;
    asm("ex2.approx.f32 %0, %1;" : "=f"(r) : "f"(x));
    return r;
}
__device__ __forceinline__ void mma_tf32(
    float& d0, float& d1, float& d2, float& d3,
    uint32_t a0, uint32_t a1, uint32_t a2, uint32_t a3,
    uint32_t b0, uint32_t b1)
{
    asm volatile(
        "mma.sync.aligned.m16n8k8.row.col.f32.tf32.tf32.f32 "
        "{%0,%1,%2,%3},{%4,%5,%6,%7},{%8,%9},{%0,%1,%2,%3};"
        : "+f"(d0), "+f"(d1), "+f"(d2), "+f"(d3)
        : "r"(a0), "r"(a1), "r"(a2), "r"(a3), "r"(b0), "r"(b1));
}
__device__ __forceinline__ void mma_bf16(
    float& d0, float& d1, float& d2, float& d3,
    uint32_t a0, uint32_t a1, uint32_t a2, uint32_t a3,
    uint32_t b0, uint32_t b1)
{
    asm volatile(
        "mma.sync.aligned.m16n8k16.row.col.f32.bf16.bf16.f32 "
        "{%0,%1,%2,%3},{%4,%5,%6,%7},{%8,%9},{%0,%1,%2,%3};"
        : "+f"(d0), "+f"(d1), "+f"(d2), "+f"(d3)
        : "r"(a0), "r"(a1), "r"(a2), "r"(a3), "r"(b0), "r"(b1));
}
__device__ __forceinline__ void cpa16(uint32_t dst, const void* src){
    asm volatile("cp.async.cg.shared.global [%0], [%1], 16;"
                 :: "r"(dst), "l"(src));
}
__device__ __forceinline__ void ldsm_x4(uint32_t& a0, uint32_t& a1,
                                        uint32_t& a2, uint32_t& a3, uint32_t addr){
    asm volatile("ldmatrix.sync.aligned.m8n8.x4.shared.b16 {%0,%1,%2,%3}, [%4];"
                 : "=r"(a0), "=r"(a1), "=r"(a2), "=r"(a3) : "r"(addr));
}

// flash smem layout (64-j tiles)
#define OFF_QS    0
#define OFF_KS    576
#define KBUF_F    768
#define VS_BYTE   14592
#define VBUF_B    9216
#define OFF_L     12864
#define SM_FLTS   12992              // 51968 B (dynamic)
#define OFF_OFIN  3648
#define OFF_OST   8000

#define LOG2E  1.4426950408889634f
#define SHIFT2 (-17.312340490667561f)   // -12 * log2(e)
#define ONESBF 0x3F803F80u

// ---------------- kernel 1: qkv via tf32 tensor cores --------------------------
// Per block: C[96 oc][64 n] = W[96][64c] * Xs[64c][64n] + bias.
// 8 warps; warp w owns n8-tile w. Mt 0: rows=q, rows+8=k. Mt 1-4: v. Mt 5: e.
__global__ __launch_bounds__(256) void qkv_kernel(
    const float* __restrict__ x,
    const float* __restrict__ qw, const float* __restrict__ qb,
    const float* __restrict__ kw, const float* __restrict__ kb,
    const float* __restrict__ vw, const float* __restrict__ vb,
    const float* __restrict__ w1, const float* __restrict__ b1)
{
    __shared__ float Ws[96*68];     // [oc][c], pitch 68 f32 (272 B)
    __shared__ float bs[96];
    __shared__ float Xs[64*68];     // [n][c], pitch 68 f32

    const int b  = blockIdx.y;
    const int n0 = blockIdx.x * 64;
    const int t  = threadIdx.x;
    const int w  = t >> 5;
    const int lane = t & 31;
    const int r  = lane >> 2;
    const int q4 = lane & 3;

    for (int i = t; i < 512;  i += 256) Ws[( 0 + (i>>6))*68 + (i&63)] = qw[i];
    for (int i = t; i < 512;  i += 256) Ws[( 8 + (i>>6))*68 + (i&63)] = kw[i];
    for (int i = t; i < 4096; i += 256) Ws[(16 + (i>>6))*68 + (i&63)] = vw[i];
    for (int i = t; i < 1024; i += 256) Ws[(80 + (i>>6))*68 + (i&63)] = w1[i];
    if (t < 96) {
        float bv;
        if      (t < 8)  bv = qb[t];
        else if (t < 16) bv = kb[t-8];
        else if (t < 80) bv = vb[t-16];
        else             bv = b1[t-80];
        bs[t] = bv;
    }
    // load x [c][n] and transpose into Xs[n][c]
    #pragma unroll
    for (int kk = 0; kk < 4; kk++) {
        int idx4 = t + 256*kk;
        int c = idx4 >> 4, n4 = idx4 & 15;
        float4 v = *((const float4*)(x + ((size_t)b*CCH + c)*NN + n0) + n4);
        Xs[(n4*4 + 0)*68 + c] = v.x;
        Xs[(n4*4 + 1)*68 + c] = v.y;
        Xs[(n4*4 + 2)*68 + c] = v.z;
        Xs[(n4*4 + 3)*68 + c] = v.w;
    }
    __syncthreads();

    // ldmatrix lane addresses
    const uint32_t wlm = (uint32_t)__cvta_generic_to_shared(Ws)
        + (uint32_t)((((lane & 7) + ((lane >> 3) & 1)*8)*68)*4
                     + ((lane >> 4) & 1)*16);
    const uint32_t xlm = (uint32_t)__cvta_generic_to_shared(Xs)
        + (uint32_t)(((w*8 + (lane & 7))*68)*4 + ((lane >> 3) & 3)*16);

    float acc[6][4];
    #pragma unroll
    for (int Mt = 0; Mt < 6; Mt++) {
        float blo = bs[Mt*16 + r], bhi = bs[Mt*16 + r + 8];
        acc[Mt][0] = blo; acc[Mt][1] = blo;
        acc[Mt][2] = bhi; acc[Mt][3] = bhi;
    }

    #pragma unroll
    for (int kp = 0; kp < 4; kp++) {
        uint32_t xb0, xb1, xb2, xb3;
        ldsm_x4(xb0, xb1, xb2, xb3, xlm + kp*64);     // ksteps 2kp, 2kp+1
        #pragma unroll
        for (int Mt = 0; Mt < 6; Mt++) {
            uint32_t a0, a1, a2, a3;
            ldsm_x4(a0, a1, a2, a3, wlm + (uint32_t)(Mt*16*68*4 + (2*kp)*32));
            mma_tf32(acc[Mt][0], acc[Mt][1], acc[Mt][2], acc[Mt][3],
                     a0, a1, a2, a3, xb0, xb1);
            ldsm_x4(a0, a1, a2, a3, wlm + (uint32_t)(Mt*16*68*4 + (2*kp+1)*32));
            mma_tf32(acc[Mt][0], acc[Mt][1], acc[Mt][2], acc[Mt][3],
                     a0, a1, a2, a3, xb2, xb3);
        }
    }

    // epilogue: thread owns n = nn, nn+1 for rows (Mt*16+r) and (Mt*16+r+8)
    const int nn = n0 + w*8 + 2*q4;
    // Mt 0: q (rows r), k (rows r+8)
    {
        float2 qv = make_float2(to_tf32(acc[0][0]), to_tf32(acc[0][1]));
        *(float2*)(g_q + ((size_t)b*DQK + r)*NN + nn) = qv;
        g_k[((size_t)b*NN + nn    )*DQK + r] = to_tf32(acc[0][2]);
        g_k[((size_t)b*NN + nn + 1)*DQK + r] = to_tf32(acc[0][3]);
    }
    // Mt 1-4: v channels (Mt-1)*16 + r and +8
    #pragma unroll
    for (int Mt = 1; Mt < 5; Mt++) {
        int c1 = (Mt-1)*16 + r;
        *(uint32_t*)(g_v + ((size_t)b*CCH + c1    )*NN + nn) =
            pack_bf16(acc[Mt][0], acc[Mt][1]);
        *(uint32_t*)(g_v + ((size_t)b*CCH + c1 + 8)*NN + nn) =
            pack_bf16(acc[Mt][2], acc[Mt][3]);
    }
    // Mt 5: e/ev channels r and r+8
    {
        float e0 = __expf(acc[5][0]), e1 = __expf(acc[5][1]);
        float e2 = __expf(acc[5][2]), e3 = __expf(acc[5][3]);
        size_t o0 = ((size_t)b*FCH + r    )*NN + nn;
        size_t o1 = ((size_t)b*FCH + r + 8)*NN + nn;
        *(float2*)(g_e  + o0) = make_float2(e0, e1);
        *(float2*)(g_ev + o0) = make_float2(e0*acc[5][0], e1*acc[5][1]);
        *(float2*)(g_e  + o1) = make_float2(e2, e3);
        *(float2*)(g_ev + o1) = make_float2(e2*acc[5][2], e3*acc[5][3]);
    }
}

// ---------------- kernel 2: softpool -------------------------------------------
__global__ void softpool_kernel()
{
    int idx = blockIdx.x*blockDim.x + threadIdx.x;
    if (idx >= BATCH*FCH*400) return;
    int ox = idx % 20, oy = (idx/20) % 20;
    int c  = (idx/400) % FCH, b = idx/(400*FCH);
    size_t base = ((size_t)b*FCH + c)*NN + (oy*3)*64 + ox*3;
    const float* se  = g_e  + base;
    const float* sev = g_ev + base;
    float num = 0.f, den = 0.f;
    #pragma unroll
    for (int ky = 0; ky < 7; ky++)
        #pragma unroll
        for (int kx = 0; kx < 7; kx++) {
            num += sev[ky*64 + kx];
            den += se [ky*64 + kx];
        }
    g_y2[idx] = num/den;
}

// ---------------- kernel 3: conv2 (redundant) -> conv3(4 oc) + sigmoid ---------
__global__ __launch_bounds__(256) void conv23_kernel(
    const float* __restrict__ w2, const float* __restrict__ b2,
    const float* __restrict__ w3, const float* __restrict__ b3)
{
    __shared__ float y2s[FCH*400];
    __shared__ float y3s[FCH*100];
    const int b  = blockIdx.x >> 4;
    const int og = blockIdx.x & 15;
    const int t  = threadIdx.x;

    for (int o = t; o < FCH*400; o += 256) y2s[o] = g_y2[(size_t)b*FCH*400 + o];
    __syncthreads();

    for (int o = t; o < FCH*100; o += 256) {
        int ox = o % 10, oy = (o/10) % 10, oc = o/100;
        float acc = b2[oc];
        for (int ic = 0; ic < FCH; ic++) {
            const float* src = y2s + ic*400;
            const float* wr  = w2 + (oc*FCH + ic)*9;
            #pragma unroll
            for (int ky = 0; ky < 3; ky++) {
                int iy = oy*2 - 1 + ky;
                if (iy < 0 || iy >= 20) continue;
                #pragma unroll
                for (int kx = 0; kx < 3; kx++) {
                    int ix = ox*2 - 1 + kx;
                    if (ix < 0 || ix >= 20) continue;
                    acc += wr[ky*3+kx] * src[iy*20 + ix];
                }
            }
        }
        y3s[o] = acc;
    }
    __syncthreads();

    for (int o = t; o < 400; o += 256) {
        int ox = o % 10, oy = (o/10) % 10;
        int oc = og*4 + o/100;
        float acc = b3[oc];
        for (int ic = 0; ic < FCH; ic++) {
            const float* src = y3s + ic*100;
            const float* wr  = w3 + (oc*FCH + ic)*9;
            #pragma unroll
            for (int ky = 0; ky < 3; ky++) {
                int iy = oy - 1 + ky;
                if (iy < 0 || iy >= 10) continue;
                #pragma unroll
                for (int kx = 0; kx < 3; kx++) {
                    int ix = ox - 1 + kx;
                    if (ix < 0 || ix >= 10) continue;
                    acc += wr[ky*3+kx] * src[iy*10 + ix];
                }
            }
        }
        g_y4[((size_t)b*CCH + oc)*100 + (o % 100)] = 1.f/(1.f + __expf(-acc));
    }
}

// ---------------- kernel 4: flash — interleaved exp/mma (R12, best) ------------
__global__ __launch_bounds__(256, 2) void flash_tc_kernel(
    const float* __restrict__ x, const float* __restrict__ gamma_p,
    float* __restrict__ out)
{
    extern __shared__ __align__(16) float sm[];
    const int b  = blockIdx.y;
    const int i0 = blockIdx.x * 64;
    const int t  = threadIdx.x;
    const int wg = t >> 7;
    const int tg = t & 127;
    const int w4 = tg >> 5;
    const int lane = t & 31;
    const int r  = lane >> 2;
    const int q4 = lane & 3;
    const int bar = wg + 1;

    for (int kx = t; kx < 512; kx += 256) {
        int d = kx >> 6, i = kx & 63;
        sm[OFF_QS + d*72 + i] = g_q[((size_t)b*DQK + d)*NN + i0 + i];
    }

    const int krow = tg >> 1, khalf = tg & 1;
    const float* ksrc = g_k + ((size_t)b*NN + wg*2048 + krow)*DQK + khalf*4;
    uint32_t kdst[2];
    #pragma unroll
    for (int p = 0; p < 2; p++)
        kdst[p] = (uint32_t)__cvta_generic_to_shared(
            sm + OFF_KS + (wg*2 + p)*KBUF_F + krow*12 + khalf*4);

    const __nv_bfloat16* vsrc[4];
    uint32_t vdst[2][4];
    #pragma unroll
    for (int kk = 0; kk < 4; kk++) {
        int cc = tg + 128*kk;
        int c = cc >> 3, jj = cc & 7;
        vsrc[kk] = g_v + ((size_t)b*CCH + c)*NN + wg*2048 + jj*8;
        #pragma unroll
        for (int p = 0; p < 2; p++)
            vdst[p][kk] = (uint32_t)__cvta_generic_to_shared(
                (char*)sm + VS_BYTE + (wg*2 + p)*VBUF_B + c*144 + jj*16);
    }

    const uint32_t vlm_off = (uint32_t)(((lane & 7) + ((lane >> 4) & 1)*8)*144
                                        + ((lane >> 3) & 1)*16);
    const uint32_t klm_off = (uint32_t)(((lane & 7) + ((lane >> 4) & 1)*8)*48
                                        + ((lane >> 3) & 1)*16);
    uint32_t vlm[2], klm[2];
    #pragma unroll
    for (int p = 0; p < 2; p++) {
        vlm[p] = (uint32_t)__cvta_generic_to_shared(
                     (char*)sm + VS_BYTE + (wg*2 + p)*VBUF_B) + vlm_off;
        klm[p] = (uint32_t)__cvta_generic_to_shared(
                     sm + OFF_KS + (wg*2 + p)*KBUF_F) + klm_off;
    }

    cpa16(kdst[0], ksrc);
    #pragma unroll
    for (int kk = 0; kk < 4; kk++) cpa16(vdst[0][kk], vsrc[kk]);
    asm volatile("cp.async.commit_group;");

    __syncthreads();
    const uint32_t aq0 = __float_as_uint(sm[OFF_QS +  q4   *72 + 16*w4 + r    ]);
    const uint32_t aq1 = __float_as_uint(sm[OFF_QS +  q4   *72 + 16*w4 + r + 8]);
    const uint32_t aq2 = __float_as_uint(sm[OFF_QS + (q4+4)*72 + 16*w4 + r    ]);
    const uint32_t aq3 = __float_as_uint(sm[OFF_QS + (q4+4)*72 + 16*w4 + r + 8]);

    float Oa[8][4];
    #pragma unroll
    for (int nc = 0; nc < 8; nc++)
        #pragma unroll
        for (int u = 0; u < 4; u++) Oa[nc][u] = 0.f;
    float La[4] = {0.f, 0.f, 0.f, 0.f};
    int par = 0;

    for (int it = 0; it < 32; ++it) {
        asm volatile("bar.sync %0, 128;" :: "r"(bar));
        if (it + 1 < 32) {
            int off = (it + 1)*64;
            cpa16(kdst[par^1], ksrc + (size_t)off*DQK);
            #pragma unroll
            for (int kk = 0; kk < 4; kk++) cpa16(vdst[par^1][kk], vsrc[kk] + off);
        }
        asm volatile("cp.async.commit_group;");
        asm volatile("cp.async.wait_group 1;");
        asm volatile("bar.sync %0, 128;" :: "r"(bar));

        const uint32_t kb = klm[par];
        const uint32_t vb = vlm[par];

        float P[8][4];
        #pragma unroll
        for (int g = 0; g < 4; g++) {
            uint32_t b0a, b1a, b0b, b1b;
            ldsm_x4(b0a, b1a, b0b, b1b, kb + g*768);
            P[2*g  ][0] = P[2*g  ][1] = P[2*g  ][2] = P[2*g  ][3] = 0.f;
            P[2*g+1][0] = P[2*g+1][1] = P[2*g+1][2] = P[2*g+1][3] = 0.f;
            mma_tf32(P[2*g  ][0], P[2*g  ][1], P[2*g  ][2], P[2*g  ][3],
                     aq0, aq1, aq2, aq3, b0a, b1a);
            mma_tf32(P[2*g+1][0], P[2*g+1][1], P[2*g+1][2], P[2*g+1][3],
                     aq0, aq1, aq2, aq3, b0b, b1b);
        }

        #pragma unroll
        for (int kt = 0; kt < 4; kt++) {
            float e0 = ex2f(fmaf(P[2*kt  ][0], LOG2E, SHIFT2));
            float e1 = ex2f(fmaf(P[2*kt  ][1], LOG2E, SHIFT2));
            float e2 = ex2f(fmaf(P[2*kt  ][2], LOG2E, SHIFT2));
            float e3 = ex2f(fmaf(P[2*kt  ][3], LOG2E, SHIFT2));
            float f0 = ex2f(fmaf(P[2*kt+1][0], LOG2E, SHIFT2));
            float f1 = ex2f(fmaf(P[2*kt+1][1], LOG2E, SHIFT2));
            float f2 = ex2f(fmaf(P[2*kt+1][2], LOG2E, SHIFT2));
            float f3 = ex2f(fmaf(P[2*kt+1][3], LOG2E, SHIFT2));
            uint32_t a0 = pack_bf16(e0, e1);
            uint32_t a1 = pack_bf16(e2, e3);
            uint32_t a2 = pack_bf16(f0, f1);
            uint32_t a3 = pack_bf16(f2, f3);
            mma_bf16(La[0], La[1], La[2], La[3],
                     a0, a1, a2, a3, ONESBF, ONESBF);
            #pragma unroll
            for (int ncp = 0; ncp < 4; ncp++) {
                uint32_t b0, b1, b2, b3;
                ldsm_x4(b0, b1, b2, b3, vb + ncp*2304 + kt*32);
                mma_bf16(Oa[2*ncp][0], Oa[2*ncp][1], Oa[2*ncp][2], Oa[2*ncp][3],
                         a0, a1, a2, a3, b0, b1);
                mma_bf16(Oa[2*ncp+1][0], Oa[2*ncp+1][1],
                         Oa[2*ncp+1][2], Oa[2*ncp+1][3],
                         a0, a1, a2, a3, b2, b3);
            }
        }
        par ^= 1;
    }

    __syncthreads();
    if (q4 == 0) {
        sm[OFF_L + wg*64 + 16*w4 + r    ] = La[0];
        sm[OFF_L + wg*64 + 16*w4 + r + 8] = La[2];
    }
    if (wg == 1) {
        #pragma unroll
        for (int nc = 0; nc < 8; nc++)
            #pragma unroll
            for (int u = 0; u < 4; u++) {
                int c  = nc*8 + 2*q4 + (u & 1);
                int il = 16*w4 + r + 8*(u >> 1);
                sm[OFF_OST + c*68 + il] = Oa[nc][u];
            }
    }
    __syncthreads();

    if (wg == 0) {
        int iqa = 16*w4 + r;
        float inv0 = 1.f / (sm[OFF_L + iqa    ] + sm[OFF_L + 64 + iqa    ]);
        float inv1 = 1.f / (sm[OFF_L + iqa + 8] + sm[OFF_L + 64 + iqa + 8]);
        #pragma unroll
        for (int nc = 0; nc < 8; nc++)
            #pragma unroll
            for (int u = 0; u < 4; u++) {
                int c  = nc*8 + 2*q4 + (u & 1);
                int il = 16*w4 + r + 8*(u >> 1);
                sm[OFF_OFIN + c*68 + il] =
                    (Oa[nc][u] + sm[OFF_OST + c*68 + il]) * ((u >> 1) ? inv1 : inv0);
            }
    }
    __syncthreads();

    const float gam = gamma_p[0];
    const int h = blockIdx.x;
    float sy = (h + 0.5f)*0.15625f - 0.5f;
    int   y0 = (int)floorf(sy);
    float fy = sy - (float)y0;
    int   y0c = max(y0, 0), y1c = min(y0 + 1, 9);

    #pragma unroll
    for (int kk = 0; kk < 4; kk++) {
        int idx4 = t + 256*kk;
        int c = idx4 >> 4, k4 = (idx4 & 15)*4;
        const float* yr0 = g_y4 + ((size_t)b*CCH + c)*100 + y0c*10;
        const float* yr1 = g_y4 + ((size_t)b*CCH + c)*100 + y1c*10;
        size_t off = ((size_t)b*CCH + c)*NN + i0 + k4;
        float4 xv = *(const float4*)(x + off);
        float4 g4 = *(const float4*)(x + (size_t)b*CCH*NN + i0 + k4);
        float xa[4] = {xv.x, xv.y, xv.z, xv.w};
        float ga[4] = {g4.x, g4.y, g4.z, g4.w};
        float res[4];
        #pragma unroll
        for (int u = 0; u < 4; u++) {
            int wpix = k4 + u;
            float sx = (wpix + 0.5f)*0.15625f - 0.5f;
            int   x0i = (int)floorf(sx);
            float fx = sx - (float)x0i;
            int   x0c = max(x0i, 0), x1c = min(x0i + 1, 9);
            float v00 = yr0[x0c], v01 = yr0[x1c];
            float v10 = yr1[x0c], v11 = yr1[x1c];
            float wv = (1.f-fy)*((1.f-fx)*v00 + fx*v01)
                     +       fy*((1.f-fx)*v10 + fx*v11);
            float gate = 1.f/(1.f + __expf(-ga[u]));
            res[u] = gam*sm[OFF_OFIN + c*68 + k4 + u] + xa[u]*(2.f + wv*gate);
        }
        *(float4*)(out + off) = make_float4(res[0], res[1], res[2], res[3]);
    }
}

// ---------------- launch -------------------------------------------------------
extern "C" void kernel_launch(void* const* d_in, const int* in_sizes, int n_in,
                              void* d_out, int out_size)
{
    const float* x     = (const float*)d_in[0];
    const float* qw    = (const float*)d_in[1];
    const float* qb    = (const float*)d_in[2];
    const float* kw    = (const float*)d_in[3];
    const float* kb    = (const float*)d_in[4];
    const float* vw    = (const float*)d_in[5];
    const float* vb    = (const float*)d_in[6];
    const float* gamma = (const float*)d_in[7];
    const float* w1    = (const float*)d_in[8];
    const float* b1    = (const float*)d_in[9];
    const float* w2    = (const float*)d_in[10];
    const float* b2    = (const float*)d_in[11];
    const float* w3    = (const float*)d_in[12];
    const float* b3    = (const float*)d_in[13];
    float* out = (float*)d_out;

    const int smem = SM_FLTS * 4;   // 51968 B
    cudaFuncSetAttribute(flash_tc_kernel,
                         cudaFuncAttributeMaxDynamicSharedMemorySize, smem);

    qkv_kernel<<<dim3(64, BATCH), 256>>>(x, qw, qb, kw, kb, vw, vb, w1, b1);
    softpool_kernel<<<100, 256>>>();
    conv23_kernel<<<64, 256>>>(w2, b2, w3, b3);
    flash_tc_kernel<<<dim3(64, BATCH), 256, smem>>>(x, gamma, out);
}